// round 11
// baseline (speedup 1.0000x reference)
#include <cuda_runtime.h>
#include <math.h>

#define N_NODES 50000
#define N_EDGES 800000
#define D 128
#define SCAN_B 1024
#define N_SBLK ((N_NODES + SCAN_B - 1) / SCAN_B)   // 49
#define EDGE_BLOCKS 256
#define TAIL_BLOCKS 592

// ---------------- scratch (device globals; self-restoring across replays) --
__device__ float g_xT [(size_t)N_NODES * D];   // X transposed: [N,128]
__device__ float g_xw [(size_t)N_NODES * D];   // GEMM out (L1 raw, L2 pre-scaled)
__device__ float g_f1 [(size_t)N_NODES * D];   // layer-1 output
__device__ float g_y  [(size_t)N_NODES * D];   // layer-2 output (+residual)
__device__ float g_deg[N_NODES];               // dinv = rsqrt(1 + in_deg)
__device__ int   g_hist[N_NODES];              // in-degree (zeroed by k_tail)
__device__ int   g_rowstart[N_NODES];          // CSR row starts (by dst)
__device__ int   g_cursor[N_NODES];            // fill cursors
__device__ int   g_csrc[N_EDGES];              // CSR src indices
__device__ int   g_bsum[64];                   // scan block sums
__device__ float g_cs [D];                     // col sum of y  (zeroed by gemm L1)
__device__ float g_cs2[D];                     // col sum of y^2
__device__ unsigned g_barCnt;                  // software grid barrier
__device__ volatile unsigned g_barGen;

__device__ __forceinline__ float gelu_exact(float v) {
    return v * normcdff(v);     // jax.nn.gelu(approximate=False)
}

__device__ __forceinline__ void fma2(unsigned long long& acc,
                                     unsigned long long a,
                                     unsigned long long b) {
    asm("fma.rn.f32x2 %0, %1, %2, %0;" : "+l"(acc) : "l"(a), "l"(b));
}

// All-resident software grid barrier (count+generation). Self-restoring:
// count returns to 0 after each use; gen monotonically increases (wraps ok).
__device__ __forceinline__ void gridbar() {
    __syncthreads();
    __threadfence();
    if (threadIdx.x == 0) {
        unsigned gen = g_barGen;
        if (atomicAdd(&g_barCnt, 1) == gridDim.x - 1) {
            g_barCnt = 0;
            __threadfence();
            g_barGen = gen + 1;
        } else {
            while (g_barGen == gen) { }
        }
    }
    __syncthreads();
    __threadfence();
}

// ---------------- fused CSR build: hist -> scan -> offsets -> fill ----------
// 256 blocks x 256 threads (all resident). edge_index is INT32.
__global__ void __launch_bounds__(256) k_edges(const int* __restrict__ ei) {
    __shared__ int sh[256];
    int t = threadIdx.x;
    int gtid = blockIdx.x * 256 + t;
    int gstride = gridDim.x * 256;

    // P1: in-degree histogram
    for (int e = gtid; e < N_EDGES; e += gstride)
        atomicAdd(&g_hist[ei[N_EDGES + e]], 1);
    gridbar();

    // P2: per-1024-chunk exclusive scan (+ dinv), blocks 0..48
    if (blockIdx.x < N_SBLK) {
        int base = blockIdx.x * SCAN_B + t * 4;
        int v[4];
#pragma unroll
        for (int i = 0; i < 4; i++) {
            int idx = base + i;
            v[i] = (idx < N_NODES) ? g_hist[idx] : 0;
            if (idx < N_NODES) g_deg[idx] = rsqrtf((float)v[i] + 1.0f);
        }
        int s = v[0] + v[1] + v[2] + v[3];
        sh[t] = s;
        __syncthreads();
        for (int off = 1; off < 256; off <<= 1) {
            int x = (t >= off) ? sh[t - off] : 0;
            __syncthreads();
            sh[t] += x;
            __syncthreads();
        }
        int excl = sh[t] - s;
#pragma unroll
        for (int i = 0; i < 4; i++) {
            int idx = base + i;
            if (idx < N_NODES) g_rowstart[idx] = excl;
            excl += v[i];
        }
        if (t == 255) g_bsum[blockIdx.x] = sh[255];
    }
    gridbar();

    // P3: scan the 49 block sums (block 0)
    if (blockIdx.x == 0) {
        int v = 0;
        if (t < 64) { v = (t < N_SBLK) ? g_bsum[t] : 0; sh[t] = v; }
        __syncthreads();
        for (int off = 1; off < 64; off <<= 1) {
            int x = (t < 64 && t >= off) ? sh[t - off] : 0;
            __syncthreads();
            if (t < 64) sh[t] += x;
            __syncthreads();
        }
        if (t < 64) g_bsum[t] = sh[t] - v;   // exclusive
    }
    gridbar();

    // P4: apply block offsets, init cursors
    for (int i = gtid; i < N_NODES; i += gstride) {
        int rs = g_rowstart[i] + g_bsum[i >> 10];
        g_rowstart[i] = rs;
        g_cursor[i]   = rs;
    }
    gridbar();

    // P5: CSR fill
    for (int e = gtid; e < N_EDGES; e += gstride) {
        int s = ei[e];
        int d = ei[N_EDGES + e];
        int pos = atomicAdd(&g_cursor[d], 1);
        g_csrc[pos] = s;
    }
}

// ---------------- transpose X [128,N] -> xT [N,128] ------------------------
__global__ void k_transpose(const float* __restrict__ X) {
    __shared__ float s[32][33];
    int n0 = blockIdx.x * 32;
    int f0 = blockIdx.y * 32;
    int tx = threadIdx.x, ty = threadIdx.y;          // (32, 8)
    int n = n0 + tx;
#pragma unroll
    for (int i = 0; i < 4; i++) {
        int f = f0 + ty + i * 8;
        if (n < N_NODES) s[ty + i * 8][tx] = X[(size_t)f * N_NODES + n];
    }
    __syncthreads();
#pragma unroll
    for (int i = 0; i < 4; i++) {
        int n2 = n0 + ty + i * 8;
        int f2 = f0 + tx;
        if (n2 < N_NODES) g_xT[(size_t)n2 * D + f2] = s[tx][ty + i * 8];
    }
}

// ---------------- GEMM (f32x2) ----------------------------------------------
// Layer 1 (src_sel=0): g_xw = A @ W          (raw; dinv applied in agg stage 0)
// Layer 2 (src_sel=1): g_xw = (A @ W)*dinv   (pre-scaled fast path)
__global__ void __launch_bounds__(256) k_gemm(int src_sel,
                                              const float* __restrict__ W) {
    const float* __restrict__ A = src_sel ? g_f1 : g_xT;
    if (src_sel == 0 && blockIdx.x == 0 && threadIdx.x < D) {
        g_cs[threadIdx.x] = 0.0f;
        g_cs2[threadIdx.x] = 0.0f;
    }
    __shared__ float2 As2[128][16];    // 16 KB: (a,a) pairs, 16-col k-chunk
    __shared__ float  Ws[16][132];     // 8.25 KB padded
    int t  = threadIdx.x;
    int tx = t & 15;                   // column group (8 cols)
    int ty = t >> 4;                   // node group (8 nodes)
    int nbase = blockIdx.x * 128;

    unsigned long long acc[8][4];
#pragma unroll
    for (int i = 0; i < 8; i++)
#pragma unroll
        for (int p = 0; p < 4; p++) acc[i][p] = 0ull;

    for (int fc = 0; fc < D; fc += 16) {
#pragma unroll
        for (int k = 0; k < 8; k++) {           // 128x16 A chunk (dup pairs)
            int idx = t + k * 256;
            int r = idx >> 4, c = idx & 15;
            int n = nbase + r;
            float v = (n < N_NODES) ? A[(size_t)n * D + fc + c] : 0.0f;
            As2[r][c] = make_float2(v, v);
        }
#pragma unroll
        for (int k = 0; k < 8; k++) {           // 16x128 W chunk
            int idx = t + k * 256;
            int r = idx >> 7, c = idx & 127;
            Ws[r][c] = W[(fc + r) * D + c];
        }
        __syncthreads();
#pragma unroll
        for (int ff = 0; ff < 16; ff++) {
            const unsigned long long* wrow =
                (const unsigned long long*)&Ws[ff][tx * 8];
            unsigned long long w0 = wrow[0];
            unsigned long long w1 = wrow[1];
            unsigned long long w2 = wrow[2];
            unsigned long long w3 = wrow[3];
#pragma unroll
            for (int i = 0; i < 8; i++) {
                unsigned long long a2 =
                    *(const unsigned long long*)&As2[ty * 8 + i][ff];
                fma2(acc[i][0], a2, w0);
                fma2(acc[i][1], a2, w1);
                fma2(acc[i][2], a2, w2);
                fma2(acc[i][3], a2, w3);
            }
        }
        __syncthreads();
    }

#pragma unroll
    for (int i = 0; i < 8; i++) {
        int node = nbase + ty * 8 + i;
        if (node >= N_NODES) continue;
        float di = src_sel ? g_deg[node] : 1.0f;
        size_t off = (size_t)node * D + tx * 8;
        float2 p0 = *(float2*)&acc[i][0];
        float2 p1 = *(float2*)&acc[i][1];
        float2 p2 = *(float2*)&acc[i][2];
        float2 p3 = *(float2*)&acc[i][3];
        ((float4*)(g_xw + off))[0] =
            make_float4(p0.x * di, p0.y * di, p1.x * di, p1.y * di);
        ((float4*)(g_xw + off))[1] =
            make_float4(p2.x * di, p2.y * di, p3.x * di, p3.y * di);
    }
}

// ---------------- agg stage 0: CSR gather + MessageNorm + GELU -------------
// msg = dinv[d]*(dinv[d]*xw[d] + sum dinv[s]*xw[s]) + b   (xw raw)
__global__ void __launch_bounds__(512) k_agg0(const float* __restrict__ bias,
                                              const float* __restrict__ scale) {
    int gw = (blockIdx.x * blockDim.x + threadIdx.x) >> 5;
    if (gw >= N_NODES) return;
    int lane = threadIdx.x & 31;

    const float4* xw4 = (const float4*)g_xw;
    float nd = g_deg[gw];
    float4 acc = xw4[(size_t)gw * 32 + lane];
    acc.x *= nd; acc.y *= nd; acc.z *= nd; acc.w *= nd;
    int rs  = g_rowstart[gw];
    int end = rs + g_hist[gw];
    int e = rs;
    for (; e + 4 <= end; e += 4) {
        int s0 = g_csrc[e],     s1 = g_csrc[e + 1];
        int s2 = g_csrc[e + 2], s3 = g_csrc[e + 3];
        float n0 = g_deg[s0], n1 = g_deg[s1], n2 = g_deg[s2], n3 = g_deg[s3];
        float4 v0 = xw4[(size_t)s0 * 32 + lane];
        float4 v1 = xw4[(size_t)s1 * 32 + lane];
        float4 v2 = xw4[(size_t)s2 * 32 + lane];
        float4 v3 = xw4[(size_t)s3 * 32 + lane];
        acc.x += (v0.x*n0 + v1.x*n1) + (v2.x*n2 + v3.x*n3);
        acc.y += (v0.y*n0 + v1.y*n1) + (v2.y*n2 + v3.y*n3);
        acc.z += (v0.z*n0 + v1.z*n1) + (v2.z*n2 + v3.z*n3);
        acc.w += (v0.w*n0 + v1.w*n1) + (v2.w*n2 + v3.w*n3);
    }
    for (; e < end; e++) {
        int s0 = g_csrc[e];
        float n0 = g_deg[s0];
        float4 v = xw4[(size_t)s0 * 32 + lane];
        acc.x += v.x*n0; acc.y += v.y*n0; acc.z += v.z*n0; acc.w += v.w*n0;
    }

    float4 bb = ((const float4*)bias)[lane];
    float4 m = make_float4(acc.x * nd + bb.x, acc.y * nd + bb.y,
                           acc.z * nd + bb.z, acc.w * nd + bb.w);

    size_t off = (size_t)gw * D;
    float4 xv = ((const float4*)(g_xT + off))[lane];

    float ms = m.x*m.x + m.y*m.y + m.z*m.z + m.w*m.w;
    float xs = xv.x*xv.x + xv.y*xv.y + xv.z*xv.z + xv.w*xv.w;
#pragma unroll
    for (int o = 16; o; o >>= 1) {
        ms += __shfl_xor_sync(0xFFFFFFFFu, ms, o);
        xs += __shfl_xor_sync(0xFFFFFFFFu, xs, o);
    }
    float coef = scale[0] * sqrtf(xs) / fmaxf(sqrtf(ms), 1e-12f);

    float4 r;
    r.x = gelu_exact(xv.x + coef * m.x);
    r.y = gelu_exact(xv.y + coef * m.y);
    r.z = gelu_exact(xv.z + coef * m.z);
    r.w = gelu_exact(xv.w + coef * m.w);
    ((float4*)(g_f1 + off))[lane] = r;
}

// ---------------- tail: agg stage 1 + stats + GraphNorm + GELU (persistent) -
// 592 blocks x 256 threads, all resident (<=64 regs via launch_bounds).
__global__ void __launch_bounds__(256, 4) k_tail(const float* __restrict__ bias,
                                                 const float* __restrict__ scale,
                                                 const float* __restrict__ gnw,
                                                 const float* __restrict__ gnb,
                                                 const float* __restrict__ gnm,
                                                 float* __restrict__ out) {
    __shared__ float s_cs[D], s_cs2[D];
    int t = threadIdx.x;
    if (t < D) { s_cs[t] = 0.0f; s_cs2[t] = 0.0f; }
    __syncthreads();

    int lane = t & 31;
    int warps = (gridDim.x * 256) >> 5;
    float sc = scale[0];
    const float4* xw4 = (const float4*)g_xw;

    // ---- phase 1: aggregation + MessageNorm + GELU + residual + stats ----
    for (int gw = (blockIdx.x * 256 + t) >> 5; gw < N_NODES; gw += warps) {
        float nd = g_deg[gw];
        float4 acc = xw4[(size_t)gw * 32 + lane];       // pre-scaled self term
        int rs  = g_rowstart[gw];
        int end = rs + g_hist[gw];
        int e = rs;
        for (; e + 8 <= end; e += 8) {
            int s0 = g_csrc[e],     s1 = g_csrc[e + 1];
            int s2 = g_csrc[e + 2], s3 = g_csrc[e + 3];
            int s4 = g_csrc[e + 4], s5 = g_csrc[e + 5];
            int s6 = g_csrc[e + 6], s7 = g_csrc[e + 7];
            float4 v0 = xw4[(size_t)s0 * 32 + lane];
            float4 v1 = xw4[(size_t)s1 * 32 + lane];
            float4 v2 = xw4[(size_t)s2 * 32 + lane];
            float4 v3 = xw4[(size_t)s3 * 32 + lane];
            float4 v4 = xw4[(size_t)s4 * 32 + lane];
            float4 v5 = xw4[(size_t)s5 * 32 + lane];
            float4 v6 = xw4[(size_t)s6 * 32 + lane];
            float4 v7 = xw4[(size_t)s7 * 32 + lane];
            acc.x += ((v0.x + v1.x) + (v2.x + v3.x)) + ((v4.x + v5.x) + (v6.x + v7.x));
            acc.y += ((v0.y + v1.y) + (v2.y + v3.y)) + ((v4.y + v5.y) + (v6.y + v7.y));
            acc.z += ((v0.z + v1.z) + (v2.z + v3.z)) + ((v4.z + v5.z) + (v6.z + v7.z));
            acc.w += ((v0.w + v1.w) + (v2.w + v3.w)) + ((v4.w + v5.w) + (v6.w + v7.w));
        }
        for (; e < end; e++) {
            float4 v = xw4[(size_t)g_csrc[e] * 32 + lane];
            acc.x += v.x; acc.y += v.y; acc.z += v.z; acc.w += v.w;
        }

        float4 bb = ((const float4*)bias)[lane];
        float4 m = make_float4(acc.x * nd + bb.x, acc.y * nd + bb.y,
                               acc.z * nd + bb.z, acc.w * nd + bb.w);
        size_t off = (size_t)gw * D;
        float4 xv = ((const float4*)(g_f1 + off))[lane];

        float ms = m.x*m.x + m.y*m.y + m.z*m.z + m.w*m.w;
        float xs = xv.x*xv.x + xv.y*xv.y + xv.z*xv.z + xv.w*xv.w;
#pragma unroll
        for (int o = 16; o; o >>= 1) {
            ms += __shfl_xor_sync(0xFFFFFFFFu, ms, o);
            xs += __shfl_xor_sync(0xFFFFFFFFu, xs, o);
        }
        float coef = sc * sqrtf(xs) / fmaxf(sqrtf(ms), 1e-12f);

        float4 rv = ((const float4*)(g_xT + off))[lane];
        float4 r;
        r.x = gelu_exact(xv.x + coef * m.x) + rv.x;
        r.y = gelu_exact(xv.y + coef * m.y) + rv.y;
        r.z = gelu_exact(xv.z + coef * m.z) + rv.z;
        r.w = gelu_exact(xv.w + coef * m.w) + rv.w;
        ((float4*)(g_y + off))[lane] = r;

        int c0 = lane * 4;
        atomicAdd(&s_cs [c0    ], r.x); atomicAdd(&s_cs2[c0    ], r.x * r.x);
        atomicAdd(&s_cs [c0 + 1], r.y); atomicAdd(&s_cs2[c0 + 1], r.y * r.y);
        atomicAdd(&s_cs [c0 + 2], r.z); atomicAdd(&s_cs2[c0 + 2], r.z * r.z);
        atomicAdd(&s_cs [c0 + 3], r.w); atomicAdd(&s_cs2[c0 + 3], r.w * r.w);
    }
    __syncthreads();
    if (t < D) {
        atomicAdd(&g_cs [t], s_cs [t]);
        atomicAdd(&g_cs2[t], s_cs2[t]);
    }
    gridbar();

    // ---- phase 2: GraphNorm + GELU (+ restore g_hist = 0) ----
    const float invN = 1.0f / (float)N_NODES;
    int gtid = blockIdx.x * 256 + t;
    int gstride = gridDim.x * 256;
    for (int idx = gtid; idx < N_NODES * D; idx += gstride) {
        if (idx < N_NODES) g_hist[idx] = 0;     // self-restore for next replay
        int c = idx & (D - 1);
        float mean = g_cs[c]  * invN;
        float ey2  = g_cs2[c] * invN;
        float msc  = gnm[c];
        float sub  = g_y[idx] - mean * msc;
        float var  = ey2 - 2.0f * msc * mean * mean + msc * msc * mean * mean;
        float o = gnw[c] * sub * rsqrtf(var + 1e-5f) + gnb[c];
        out[idx] = gelu_exact(o);
    }
}

// ---------------- launch ----------------------------------------------------
extern "C" void kernel_launch(void* const* d_in, const int* in_sizes, int n_in,
                              void* d_out, int out_size) {
    const float* X   = (const float*)d_in[0];
    const int*   ei  = (const int*)  d_in[1];     // int32 (JAX x64 disabled)
    const float* W1  = (const float*)d_in[2];
    const float* b1  = (const float*)d_in[3];
    const float* s1  = (const float*)d_in[4];
    const float* W2  = (const float*)d_in[5];
    const float* b2  = (const float*)d_in[6];
    const float* s2  = (const float*)d_in[7];
    const float* gnw = (const float*)d_in[8];
    const float* gnb = (const float*)d_in[9];
    const float* gnm = (const float*)d_in[10];
    float* out = (float*)d_out;

    int gemm_blocks = (N_NODES + 127) / 128;
    int agg_blocks  = (N_NODES * 32 + 511) / 512;
    dim3 tg((N_NODES + 31) / 32, D / 32);

    cudaStream_t se;                       // edge-pipeline branch
    cudaStreamCreateWithFlags(&se, cudaStreamNonBlocking);
    cudaEvent_t evFork, evJoin;
    cudaEventCreateWithFlags(&evFork, cudaEventDisableTiming);
    cudaEventCreateWithFlags(&evJoin, cudaEventDisableTiming);

    // fork: edge pipeline on se, dense pipeline on default stream
    cudaEventRecord(evFork, 0);
    cudaStreamWaitEvent(se, evFork, 0);

    // branch A (se): fused CSR build (1 kernel, software grid barriers)
    k_edges<<<EDGE_BLOCKS, 256, 0, se>>>(ei);
    cudaEventRecord(evJoin, se);

    // branch B (default): transpose + raw GEMM layer 1
    k_transpose<<<tg, dim3(32, 8)>>>(X);
    k_gemm <<<gemm_blocks, 256>>>(0, W1);

    // join
    cudaStreamWaitEvent(0, evJoin, 0);

    // ---- layer 1 aggregation (applies dinv per edge) ----
    k_agg0 <<<agg_blocks, 512>>>(b1, s1);

    // ---- layer 2 GEMM (pre-scaled path) ----
    k_gemm <<<gemm_blocks, 256>>>(1, W2);

    // ---- layer 2 agg + GraphNorm + GELU (fused persistent tail) ----
    k_tail <<<TAIL_BLOCKS, 256>>>(b2, s2, gnw, gnb, gnm, out);

    cudaEventDestroy(evFork);
    cudaEventDestroy(evJoin);
    cudaStreamDestroy(se);
}

// round 12
// speedup vs baseline: 1.0367x; 1.0367x over previous
#include <cuda_runtime.h>
#include <math.h>

#define N_NODES 50000
#define N_EDGES 800000
#define D 128
#define SCAN_B 1024
#define N_SBLK ((N_NODES + SCAN_B - 1) / SCAN_B)   // 49

// ---------------- scratch (device globals; self-restoring across replays) --
__device__ float g_xT [(size_t)N_NODES * D];   // X transposed: [N,128]
__device__ float g_xw [(size_t)N_NODES * D];   // GEMM out (L1 raw, L2 pre-scaled)
__device__ float g_f1 [(size_t)N_NODES * D];   // layer-1 output
__device__ float g_y  [(size_t)N_NODES * D];   // layer-2 output (+residual)
__device__ float g_deg[N_NODES];               // dinv = rsqrt(1 + in_deg)
__device__ int   g_hist[N_NODES];              // in-degree (zeroed by k_final)
__device__ int   g_rowstart[N_NODES];          // CSR row starts (by dst)
__device__ int   g_cursor[N_NODES];            // fill cursors
__device__ int   g_csrc[N_EDGES];              // CSR src indices
__device__ int   g_bsum[64];                   // scan block sums
__device__ float g_cs [D];                     // col sum of y  (zeroed by gemm L1)
__device__ float g_cs2[D];                     // col sum of y^2

__device__ __forceinline__ float gelu_exact(float v) {
    return v * normcdff(v);     // jax.nn.gelu(approximate=False)
}

// packed f32x2 helpers (Blackwell FFMA2/FADD2 — PTX-only)
__device__ __forceinline__ void fma2(unsigned long long& acc,
                                     unsigned long long a,
                                     unsigned long long b) {
    asm("fma.rn.f32x2 %0, %1, %2, %0;" : "+l"(acc) : "l"(a), "l"(b));
}
__device__ __forceinline__ unsigned long long addp(unsigned long long a,
                                                   unsigned long long b) {
    unsigned long long r;
    asm("add.rn.f32x2 %0, %1, %2;" : "=l"(r) : "l"(a), "l"(b));
    return r;
}
__device__ __forceinline__ unsigned long long fmap(unsigned long long a,
                                                   unsigned long long b,
                                                   unsigned long long c) {
    unsigned long long r;
    asm("fma.rn.f32x2 %0, %1, %2, %3;" : "=l"(r) : "l"(a), "l"(b), "l"(c));
    return r;
}
__device__ __forceinline__ unsigned long long packf(float v) {
    unsigned long long r;
    unsigned u = __float_as_uint(v);
    asm("mov.b64 %0, {%1, %1};" : "=l"(r) : "r"(u));
    return r;
}

// ---------------- in-degree histogram (edge_index is INT32) ----------------
__global__ void k_deg(const int* __restrict__ ei) {
    int e = blockIdx.x * blockDim.x + threadIdx.x;
    if (e < N_EDGES) atomicAdd(&g_hist[ei[N_EDGES + e]], 1);
}

// ---------------- scan pass 1 (+ fused dinv = rsqrt(deg+1)) ----------------
__global__ void k_scan1() {
    __shared__ int sh[SCAN_B];
    int t = threadIdx.x;
    int i = blockIdx.x * SCAN_B + t;
    int v = (i < N_NODES) ? g_hist[i] : 0;
    if (i < N_NODES) g_deg[i] = rsqrtf((float)v + 1.0f);
    sh[t] = v;
    __syncthreads();
    for (int off = 1; off < SCAN_B; off <<= 1) {
        int x = (t >= off) ? sh[t - off] : 0;
        __syncthreads();
        sh[t] += x;
        __syncthreads();
    }
    if (i < N_NODES) g_rowstart[i] = sh[t] - v;
    if (t == SCAN_B - 1) g_bsum[blockIdx.x] = sh[t];
}

// ---------------- scan pass 2+3 fused: block offsets + apply ----------------
__global__ void k_scan3() {
    __shared__ int sb[64];
    int t = threadIdx.x;
    if (t < 64) sb[t] = (t < N_SBLK) ? g_bsum[t] : 0;
    __syncthreads();
#pragma unroll
    for (int off = 1; off < 64; off <<= 1) {
        int x = (t < 64 && t >= off) ? sb[t - off] : 0;
        __syncthreads();
        if (t < 64) sb[t] += x;
        __syncthreads();
    }
    int i = blockIdx.x * blockDim.x + t;
    if (i < N_NODES) {
        int blk = i / SCAN_B;
        int add = blk ? sb[blk - 1] : 0;
        int rs = g_rowstart[i] + add;
        g_rowstart[i] = rs;
        g_cursor[i]   = rs;
    }
}

// ---------------- CSR fill ---------------------------------------------------
__global__ void k_fill(const int* __restrict__ ei) {
    int e = blockIdx.x * blockDim.x + threadIdx.x;
    if (e < N_EDGES) {
        int s = ei[e];
        int d = ei[N_EDGES + e];
        int pos = atomicAdd(&g_cursor[d], 1);
        g_csrc[pos] = s;
    }
}

// ---------------- transpose X [128,N] -> xT [N,128] ------------------------
__global__ void k_transpose(const float* __restrict__ X) {
    __shared__ float s[32][33];
    int n0 = blockIdx.x * 32;
    int f0 = blockIdx.y * 32;
    int tx = threadIdx.x, ty = threadIdx.y;          // (32, 8)
    int n = n0 + tx;
#pragma unroll
    for (int i = 0; i < 4; i++) {
        int f = f0 + ty + i * 8;
        if (n < N_NODES) s[ty + i * 8][tx] = X[(size_t)f * N_NODES + n];
    }
    __syncthreads();
#pragma unroll
    for (int i = 0; i < 4; i++) {
        int n2 = n0 + ty + i * 8;
        int f2 = f0 + tx;
        if (n2 < N_NODES) g_xT[(size_t)n2 * D + f2] = s[tx][ty + i * 8];
    }
}

// ---------------- GEMM (f32x2) ----------------------------------------------
// Layer 1 (src_sel=0): g_xw = A @ W          (raw; dinv applied in agg stage 0)
// Layer 2 (src_sel=1): g_xw = (A @ W)*dinv   (pre-scaled fast path)
__global__ void __launch_bounds__(256) k_gemm(int src_sel,
                                              const float* __restrict__ W) {
    const float* __restrict__ A = src_sel ? g_f1 : g_xT;
    if (src_sel == 0 && blockIdx.x == 0 && threadIdx.x < D) {
        g_cs[threadIdx.x] = 0.0f;
        g_cs2[threadIdx.x] = 0.0f;
    }
    __shared__ float2 As2[128][16];    // 16 KB: (a,a) pairs, 16-col k-chunk
    __shared__ float  Ws[16][132];     // 8.25 KB padded
    int t  = threadIdx.x;
    int tx = t & 15;                   // column group (8 cols)
    int ty = t >> 4;                   // node group (8 nodes)
    int nbase = blockIdx.x * 128;

    unsigned long long acc[8][4];
#pragma unroll
    for (int i = 0; i < 8; i++)
#pragma unroll
        for (int p = 0; p < 4; p++) acc[i][p] = 0ull;

    for (int fc = 0; fc < D; fc += 16) {
#pragma unroll
        for (int k = 0; k < 8; k++) {           // 128x16 A chunk (dup pairs)
            int idx = t + k * 256;
            int r = idx >> 4, c = idx & 15;
            int n = nbase + r;
            float v = (n < N_NODES) ? A[(size_t)n * D + fc + c] : 0.0f;
            As2[r][c] = make_float2(v, v);
        }
#pragma unroll
        for (int k = 0; k < 8; k++) {           // 16x128 W chunk
            int idx = t + k * 256;
            int r = idx >> 7, c = idx & 127;
            Ws[r][c] = W[(fc + r) * D + c];
        }
        __syncthreads();
#pragma unroll
        for (int ff = 0; ff < 16; ff++) {
            const unsigned long long* wrow =
                (const unsigned long long*)&Ws[ff][tx * 8];
            unsigned long long w0 = wrow[0];
            unsigned long long w1 = wrow[1];
            unsigned long long w2 = wrow[2];
            unsigned long long w3 = wrow[3];
#pragma unroll
            for (int i = 0; i < 8; i++) {
                unsigned long long a2 =
                    *(const unsigned long long*)&As2[ty * 8 + i][ff];
                fma2(acc[i][0], a2, w0);
                fma2(acc[i][1], a2, w1);
                fma2(acc[i][2], a2, w2);
                fma2(acc[i][3], a2, w3);
            }
        }
        __syncthreads();
    }

#pragma unroll
    for (int i = 0; i < 8; i++) {
        int node = nbase + ty * 8 + i;
        if (node >= N_NODES) continue;
        float di = src_sel ? g_deg[node] : 1.0f;
        size_t off = (size_t)node * D + tx * 8;
        float2 p0 = *(float2*)&acc[i][0];
        float2 p1 = *(float2*)&acc[i][1];
        float2 p2 = *(float2*)&acc[i][2];
        float2 p3 = *(float2*)&acc[i][3];
        ((float4*)(g_xw + off))[0] =
            make_float4(p0.x * di, p0.y * di, p1.x * di, p1.y * di);
        ((float4*)(g_xw + off))[1] =
            make_float4(p2.x * di, p2.y * di, p3.x * di, p3.y * di);
    }
}

// ---------------- fused CSR gather + MessageNorm + GELU (+stats) -----------
// stage 0: xw raw   -> msg = dinv[d]*(dinv[d]*xw[d] + sum dinv[s]*xw[s]) + b
// stage 1: xw scaled-> msg = dinv[d]*(xw[d] + sum xw[s]) + b   (+res, +stats)
// Edge-loop arithmetic uses packed f32x2 (half the issue slots of scalar).
__global__ void __launch_bounds__(512) k_agg(int stage,
                                             const float* __restrict__ bias,
                                             const float* __restrict__ scale) {
    __shared__ float s_cs[D], s_cs2[D];
    if (stage) {
        if (threadIdx.x < D) { s_cs[threadIdx.x] = 0.0f; s_cs2[threadIdx.x] = 0.0f; }
        __syncthreads();
    }

    int gw = (blockIdx.x * blockDim.x + threadIdx.x) >> 5;
    int lane = threadIdx.x & 31;
    bool active = gw < N_NODES;
    float4 r = make_float4(0.f, 0.f, 0.f, 0.f);

    if (active) {
        const char* xwb = (const char*)g_xw + lane * 16;   // per-lane base
        float nd = g_deg[gw];

        // self-loop term
        ulonglong2 sv = *(const ulonglong2*)(xwb + (size_t)gw * 512);
        unsigned long long accA, accB;
        if (!stage) {
            unsigned long long nd2 = packf(nd);
            accA = fmap(sv.x, nd2, 0ull);
            accB = fmap(sv.y, nd2, 0ull);
        } else {
            accA = sv.x;
            accB = sv.y;
        }

        int rs  = g_rowstart[gw];
        int end = rs + g_hist[gw];
        int e = rs;
        if (stage) {
            for (; e + 8 <= end; e += 8) {
                int s0 = g_csrc[e],     s1 = g_csrc[e + 1];
                int s2 = g_csrc[e + 2], s3 = g_csrc[e + 3];
                int s4 = g_csrc[e + 4], s5 = g_csrc[e + 5];
                int s6 = g_csrc[e + 6], s7 = g_csrc[e + 7];
                ulonglong2 v0 = *(const ulonglong2*)(xwb + (size_t)s0 * 512);
                ulonglong2 v1 = *(const ulonglong2*)(xwb + (size_t)s1 * 512);
                ulonglong2 v2 = *(const ulonglong2*)(xwb + (size_t)s2 * 512);
                ulonglong2 v3 = *(const ulonglong2*)(xwb + (size_t)s3 * 512);
                ulonglong2 v4 = *(const ulonglong2*)(xwb + (size_t)s4 * 512);
                ulonglong2 v5 = *(const ulonglong2*)(xwb + (size_t)s5 * 512);
                ulonglong2 v6 = *(const ulonglong2*)(xwb + (size_t)s6 * 512);
                ulonglong2 v7 = *(const ulonglong2*)(xwb + (size_t)s7 * 512);
                // packed tree reduction (A halves and B halves independent)
                unsigned long long a01 = addp(v0.x, v1.x), a23 = addp(v2.x, v3.x);
                unsigned long long a45 = addp(v4.x, v5.x), a67 = addp(v6.x, v7.x);
                unsigned long long b01 = addp(v0.y, v1.y), b23 = addp(v2.y, v3.y);
                unsigned long long b45 = addp(v4.y, v5.y), b67 = addp(v6.y, v7.y);
                accA = addp(accA, addp(addp(a01, a23), addp(a45, a67)));
                accB = addp(accB, addp(addp(b01, b23), addp(b45, b67)));
            }
            for (; e < end; e++) {
                ulonglong2 v = *(const ulonglong2*)(xwb + (size_t)g_csrc[e] * 512);
                accA = addp(accA, v.x);
                accB = addp(accB, v.y);
            }
        } else {
            // two interleaved FFMA2 chains for latency hiding
            unsigned long long pA = 0ull, pB = 0ull;
            for (; e + 4 <= end; e += 4) {
                int s0 = g_csrc[e],     s1 = g_csrc[e + 1];
                int s2 = g_csrc[e + 2], s3 = g_csrc[e + 3];
                unsigned long long n0 = packf(g_deg[s0]);
                unsigned long long n1 = packf(g_deg[s1]);
                unsigned long long n2 = packf(g_deg[s2]);
                unsigned long long n3 = packf(g_deg[s3]);
                ulonglong2 v0 = *(const ulonglong2*)(xwb + (size_t)s0 * 512);
                ulonglong2 v1 = *(const ulonglong2*)(xwb + (size_t)s1 * 512);
                ulonglong2 v2 = *(const ulonglong2*)(xwb + (size_t)s2 * 512);
                ulonglong2 v3 = *(const ulonglong2*)(xwb + (size_t)s3 * 512);
                accA = fmap(v0.x, n0, accA);  pA = fmap(v1.x, n1, pA);
                accB = fmap(v0.y, n0, accB);  pB = fmap(v1.y, n1, pB);
                accA = fmap(v2.x, n2, accA);  pA = fmap(v3.x, n3, pA);
                accB = fmap(v2.y, n2, accB);  pB = fmap(v3.y, n3, pB);
            }
            for (; e < end; e++) {
                int s0 = g_csrc[e];
                unsigned long long n0 = packf(g_deg[s0]);
                ulonglong2 v = *(const ulonglong2*)(xwb + (size_t)s0 * 512);
                accA = fmap(v.x, n0, accA);
                accB = fmap(v.y, n0, accB);
            }
            accA = addp(accA, pA);
            accB = addp(accB, pB);
        }

        float2 aA = *(float2*)&accA;
        float2 aB = *(float2*)&accB;
        float4 bb = ((const float4*)bias)[lane];
        float4 m = make_float4(aA.x * nd + bb.x, aA.y * nd + bb.y,
                               aB.x * nd + bb.z, aB.y * nd + bb.w);

        size_t off = (size_t)gw * D;
        const float* xprev = stage ? g_f1 : g_xT;
        float4 xv = ((const float4*)(xprev + off))[lane];

        float ms = m.x*m.x + m.y*m.y + m.z*m.z + m.w*m.w;
        float xs = xv.x*xv.x + xv.y*xv.y + xv.z*xv.z + xv.w*xv.w;
#pragma unroll
        for (int o = 16; o; o >>= 1) {
            ms += __shfl_xor_sync(0xFFFFFFFFu, ms, o);
            xs += __shfl_xor_sync(0xFFFFFFFFu, xs, o);
        }
        float coef = scale[0] * sqrtf(xs) / fmaxf(sqrtf(ms), 1e-12f);

        r.x = gelu_exact(xv.x + coef * m.x);
        r.y = gelu_exact(xv.y + coef * m.y);
        r.z = gelu_exact(xv.z + coef * m.z);
        r.w = gelu_exact(xv.w + coef * m.w);

        if (stage) {
            float4 rv = ((const float4*)(g_xT + off))[lane];
            r.x += rv.x; r.y += rv.y; r.z += rv.z; r.w += rv.w;
        }
        float* out = stage ? g_y : g_f1;
        ((float4*)(out + off))[lane] = r;
    }

    if (stage) {
        if (active) {
            int c0 = lane * 4;
            atomicAdd(&s_cs [c0    ], r.x); atomicAdd(&s_cs2[c0    ], r.x * r.x);
            atomicAdd(&s_cs [c0 + 1], r.y); atomicAdd(&s_cs2[c0 + 1], r.y * r.y);
            atomicAdd(&s_cs [c0 + 2], r.z); atomicAdd(&s_cs2[c0 + 2], r.z * r.z);
            atomicAdd(&s_cs [c0 + 3], r.w); atomicAdd(&s_cs2[c0 + 3], r.w * r.w);
        }
        __syncthreads();
        if (threadIdx.x < D) {
            atomicAdd(&g_cs [threadIdx.x], s_cs [threadIdx.x]);
            atomicAdd(&g_cs2[threadIdx.x], s_cs2[threadIdx.x]);
        }
    }
}

// ---------------- finalize: GraphNorm + GELU (+ restore g_hist = 0) --------
__global__ void k_final(const float* __restrict__ gnw,
                        const float* __restrict__ gnb,
                        const float* __restrict__ gnm,
                        float* __restrict__ out) {
    const float invN = 1.0f / (float)N_NODES;
    for (int idx = blockIdx.x * blockDim.x + threadIdx.x;
         idx < N_NODES * D; idx += gridDim.x * blockDim.x) {
        if (idx < N_NODES) g_hist[idx] = 0;     // self-restore for next replay
        int c = idx & (D - 1);
        float mean = g_cs[c]  * invN;
        float ey2  = g_cs2[c] * invN;
        float msc  = gnm[c];
        float sub  = g_y[idx] - mean * msc;
        float var  = ey2 - 2.0f * msc * mean * mean + msc * msc * mean * mean;
        float o = gnw[c] * sub * rsqrtf(var + 1e-5f) + gnb[c];
        out[idx] = gelu_exact(o);
    }
}

// ---------------- launch ----------------------------------------------------
extern "C" void kernel_launch(void* const* d_in, const int* in_sizes, int n_in,
                              void* d_out, int out_size) {
    const float* X   = (const float*)d_in[0];
    const int*   ei  = (const int*)  d_in[1];     // int32 (JAX x64 disabled)
    const float* W1  = (const float*)d_in[2];
    const float* b1  = (const float*)d_in[3];
    const float* s1  = (const float*)d_in[4];
    const float* W2  = (const float*)d_in[5];
    const float* b2  = (const float*)d_in[6];
    const float* s2  = (const float*)d_in[7];
    const float* gnw = (const float*)d_in[8];
    const float* gnb = (const float*)d_in[9];
    const float* gnm = (const float*)d_in[10];
    float* out = (float*)d_out;

    const int TB = 256;
    int gemm_blocks = (N_NODES + 127) / 128;
    int agg_blocks  = (N_NODES * 32 + 511) / 512;
    dim3 tg((N_NODES + 31) / 32, D / 32);

    cudaStream_t se;                       // edge-pipeline branch
    cudaStreamCreateWithFlags(&se, cudaStreamNonBlocking);
    cudaEvent_t evFork, evJoin;
    cudaEventCreateWithFlags(&evFork, cudaEventDisableTiming);
    cudaEventCreateWithFlags(&evJoin, cudaEventDisableTiming);

    // fork: edge pipeline on se, dense pipeline on default stream
    cudaEventRecord(evFork, 0);
    cudaStreamWaitEvent(se, evFork, 0);

    // branch A (se): CSR build + dinv
    k_deg   <<<(N_EDGES + TB - 1) / TB, TB, 0, se>>>(ei);
    k_scan1 <<<N_SBLK, SCAN_B, 0, se>>>();
    k_scan3 <<<(N_NODES + TB - 1) / TB, TB, 0, se>>>();
    k_fill  <<<(N_EDGES + TB - 1) / TB, TB, 0, se>>>(ei);
    cudaEventRecord(evJoin, se);

    // branch B (default): transpose + raw GEMM layer 1
    k_transpose<<<tg, dim3(32, 8)>>>(X);
    k_gemm <<<gemm_blocks, TB>>>(0, W1);

    // join
    cudaStreamWaitEvent(0, evJoin, 0);

    // ---- layer 1 aggregation (applies dinv per edge) ----
    k_agg  <<<agg_blocks, 512>>>(0, b1, s1);

    // ---- layer 2 (pre-scaled path) ----
    k_gemm <<<gemm_blocks, TB>>>(1, W2);
    k_agg  <<<agg_blocks, 512>>>(1, b2, s2);

    // ---- GraphNorm + GELU ----
    k_final<<<4096, TB>>>(gnw, gnb, gnm, out);

    cudaEventDestroy(evFork);
    cudaEventDestroy(evJoin);
    cudaStreamDestroy(se);
}

// round 13
// speedup vs baseline: 1.0619x; 1.0243x over previous
#include <cuda_runtime.h>
#include <math.h>

#define N_NODES 50000
#define N_EDGES 800000
#define D 128
#define SCAN_B 1024
#define N_SBLK ((N_NODES + SCAN_B - 1) / SCAN_B)   // 49

// ---------------- scratch (device globals; self-restoring across replays) --
__device__ float g_xT [(size_t)N_NODES * D];   // X transposed: [N,128]
__device__ float g_xw [(size_t)N_NODES * D];   // GEMM out (L1 raw, L2 pre-scaled)
__device__ float g_f1 [(size_t)N_NODES * D];   // layer-1 output
__device__ float g_y  [(size_t)N_NODES * D];   // layer-2 output (+residual)
__device__ float g_deg[N_NODES];               // dinv = rsqrt(1 + in_deg)
__device__ int   g_hist[N_NODES];              // in-degree (zeroed by k_final)
__device__ int   g_rowstart[N_NODES];          // CSR row starts (block-LOCAL excl)
__device__ int   g_cursor[N_NODES];            // fill cursors (block-local)
__device__ int   g_csrc[N_EDGES];              // CSR src * 32 (float4-elem offset)
__device__ int   g_bsum [64];                  // scan block sums
__device__ int   g_bsumx[64];                  // exclusive block offsets
__device__ int   g_scnt;                       // scan1 completion counter (self-resets)
__device__ float g_cs [D];                     // col sum of y  (zeroed by gemm L1)
__device__ float g_cs2[D];                     // col sum of y^2

__device__ __forceinline__ float gelu_exact(float v) {
    return v * normcdff(v);     // jax.nn.gelu(approximate=False)
}

__device__ __forceinline__ void fma2(unsigned long long& acc,
                                     unsigned long long a,
                                     unsigned long long b) {
    asm("fma.rn.f32x2 %0, %1, %2, %0;" : "+l"(acc) : "l"(a), "l"(b));
}

// ---------------- in-degree histogram (edge_index is INT32) ----------------
__global__ void k_deg(const int* __restrict__ ei) {
    int e = blockIdx.x * blockDim.x + threadIdx.x;
    if (e < N_EDGES) atomicAdd(&g_hist[ei[N_EDGES + e]], 1);
}

// ---------------- scan pass 1 (+ dinv) + last-block bsum scan --------------
__global__ void k_scan1() {
    __shared__ int sh[SCAN_B];
    __shared__ bool isLast;
    int t = threadIdx.x;
    int i = blockIdx.x * SCAN_B + t;
    int v = (i < N_NODES) ? g_hist[i] : 0;
    if (i < N_NODES) g_deg[i] = rsqrtf((float)v + 1.0f);
    sh[t] = v;
    __syncthreads();
    for (int off = 1; off < SCAN_B; off <<= 1) {
        int x = (t >= off) ? sh[t - off] : 0;
        __syncthreads();
        sh[t] += x;
        __syncthreads();
    }
    if (i < N_NODES) {
        int excl = sh[t] - v;           // block-LOCAL exclusive
        g_rowstart[i] = excl;
        g_cursor[i]   = excl;
    }
    if (t == SCAN_B - 1) {
        g_bsum[blockIdx.x] = sh[t];     // block total
        __threadfence();
        isLast = (atomicAdd(&g_scnt, 1) == (int)gridDim.x - 1);
    }
    __syncthreads();
    if (isLast) {
        __threadfence();                // acquire: see all blocks' g_bsum
        int bv = 0;
        if (t < 64) { bv = (t < N_SBLK) ? g_bsum[t] : 0; sh[t] = bv; }
        __syncthreads();
        for (int off = 1; off < 64; off <<= 1) {
            int x = (t < 64 && t >= off) ? sh[t - off] : 0;
            __syncthreads();
            if (t < 64) sh[t] += x;
            __syncthreads();
        }
        if (t < 64) g_bsumx[t] = sh[t] - bv;   // exclusive offsets
        if (t == 0) g_scnt = 0;                // self-restore for next replay
    }
}

// ---------------- CSR fill (global pos = bsumx[chunk] + local cursor) ------
__global__ void k_fill(const int* __restrict__ ei) {
    int e = blockIdx.x * blockDim.x + threadIdx.x;
    if (e < N_EDGES) {
        int s = ei[e];
        int d = ei[N_EDGES + e];
        int pos = atomicAdd(&g_cursor[d], 1);
        g_csrc[g_bsumx[d >> 10] + pos] = s * 32;   // premultiplied offset
    }
}

// ---------------- transpose X [128,N] -> xT [N,128] ------------------------
__global__ void k_transpose(const float* __restrict__ X) {
    __shared__ float s[32][33];
    int n0 = blockIdx.x * 32;
    int f0 = blockIdx.y * 32;
    int tx = threadIdx.x, ty = threadIdx.y;          // (32, 8)
    int n = n0 + tx;
#pragma unroll
    for (int i = 0; i < 4; i++) {
        int f = f0 + ty + i * 8;
        if (n < N_NODES) s[ty + i * 8][tx] = X[(size_t)f * N_NODES + n];
    }
    __syncthreads();
#pragma unroll
    for (int i = 0; i < 4; i++) {
        int n2 = n0 + ty + i * 8;
        int f2 = f0 + tx;
        if (n2 < N_NODES) g_xT[(size_t)n2 * D + f2] = s[tx][ty + i * 8];
    }
}

// ---------------- GEMM (f32x2) ----------------------------------------------
// Layer 1 (src_sel=0): g_xw = A @ W          (raw; dinv applied in agg stage 0)
// Layer 2 (src_sel=1): g_xw = (A @ W)*dinv   (pre-scaled fast path)
__global__ void __launch_bounds__(256) k_gemm(int src_sel,
                                              const float* __restrict__ W) {
    const float* __restrict__ A = src_sel ? g_f1 : g_xT;
    if (src_sel == 0 && blockIdx.x == 0 && threadIdx.x < D) {
        g_cs[threadIdx.x] = 0.0f;
        g_cs2[threadIdx.x] = 0.0f;
    }
    __shared__ float2 As2[128][16];    // 16 KB: (a,a) pairs, 16-col k-chunk
    __shared__ float  Ws[16][132];     // 8.25 KB padded
    int t  = threadIdx.x;
    int tx = t & 15;                   // column group (8 cols)
    int ty = t >> 4;                   // node group (8 nodes)
    int nbase = blockIdx.x * 128;

    unsigned long long acc[8][4];
#pragma unroll
    for (int i = 0; i < 8; i++)
#pragma unroll
        for (int p = 0; p < 4; p++) acc[i][p] = 0ull;

    for (int fc = 0; fc < D; fc += 16) {
#pragma unroll
        for (int k = 0; k < 8; k++) {           // 128x16 A chunk (dup pairs)
            int idx = t + k * 256;
            int r = idx >> 4, c = idx & 15;
            int n = nbase + r;
            float v = (n < N_NODES) ? A[(size_t)n * D + fc + c] : 0.0f;
            As2[r][c] = make_float2(v, v);
        }
#pragma unroll
        for (int k = 0; k < 8; k++) {           // 16x128 W chunk
            int idx = t + k * 256;
            int r = idx >> 7, c = idx & 127;
            Ws[r][c] = W[(fc + r) * D + c];
        }
        __syncthreads();
#pragma unroll
        for (int ff = 0; ff < 16; ff++) {
            const unsigned long long* wrow =
                (const unsigned long long*)&Ws[ff][tx * 8];
            unsigned long long w0 = wrow[0];
            unsigned long long w1 = wrow[1];
            unsigned long long w2 = wrow[2];
            unsigned long long w3 = wrow[3];
#pragma unroll
            for (int i = 0; i < 8; i++) {
                unsigned long long a2 =
                    *(const unsigned long long*)&As2[ty * 8 + i][ff];
                fma2(acc[i][0], a2, w0);
                fma2(acc[i][1], a2, w1);
                fma2(acc[i][2], a2, w2);
                fma2(acc[i][3], a2, w3);
            }
        }
        __syncthreads();
    }

#pragma unroll
    for (int i = 0; i < 8; i++) {
        int node = nbase + ty * 8 + i;
        if (node >= N_NODES) continue;
        float di = src_sel ? g_deg[node] : 1.0f;
        size_t off = (size_t)node * D + tx * 8;
        float2 p0 = *(float2*)&acc[i][0];
        float2 p1 = *(float2*)&acc[i][1];
        float2 p2 = *(float2*)&acc[i][2];
        float2 p3 = *(float2*)&acc[i][3];
        ((float4*)(g_xw + off))[0] =
            make_float4(p0.x * di, p0.y * di, p1.x * di, p1.y * di);
        ((float4*)(g_xw + off))[1] =
            make_float4(p2.x * di, p2.y * di, p3.x * di, p3.y * di);
    }
}

// ---------------- fused CSR gather + MessageNorm + GELU (+stats) -----------
// stage 0: xw raw   -> msg = dinv[d]*(dinv[d]*xw[d] + sum dinv[s]*xw[s]) + b
// stage 1: xw scaled-> msg = dinv[d]*(xw[d] + sum xw[s]) + b   (+res, +stats)
// g_csrc holds src*32 (float4-element offsets); deg index = offset >> 5.
__global__ void __launch_bounds__(512) k_agg(int stage,
                                             const float* __restrict__ bias,
                                             const float* __restrict__ scale) {
    __shared__ float s_cs[D], s_cs2[D];
    if (stage) {
        if (threadIdx.x < D) { s_cs[threadIdx.x] = 0.0f; s_cs2[threadIdx.x] = 0.0f; }
        __syncthreads();
    }

    int gw = (blockIdx.x * blockDim.x + threadIdx.x) >> 5;
    int lane = threadIdx.x & 31;
    bool active = gw < N_NODES;
    float4 r = make_float4(0.f, 0.f, 0.f, 0.f);

    if (active) {
        const float4* xw4 = (const float4*)g_xw;
        float nd = g_deg[gw];
        float4 acc = xw4[(size_t)gw * 32 + lane];       // self-loop term
        if (!stage) { acc.x *= nd; acc.y *= nd; acc.z *= nd; acc.w *= nd; }
        int rs  = g_rowstart[gw] + g_bsumx[gw >> 10];   // global row start
        int end = rs + g_hist[gw];
        int e = rs;
        if (stage) {
            for (; e + 8 <= end; e += 8) {
                int s0 = g_csrc[e],     s1 = g_csrc[e + 1];
                int s2 = g_csrc[e + 2], s3 = g_csrc[e + 3];
                int s4 = g_csrc[e + 4], s5 = g_csrc[e + 5];
                int s6 = g_csrc[e + 6], s7 = g_csrc[e + 7];
                float4 v0 = xw4[s0 + lane];
                float4 v1 = xw4[s1 + lane];
                float4 v2 = xw4[s2 + lane];
                float4 v3 = xw4[s3 + lane];
                float4 v4 = xw4[s4 + lane];
                float4 v5 = xw4[s5 + lane];
                float4 v6 = xw4[s6 + lane];
                float4 v7 = xw4[s7 + lane];
                acc.x += ((v0.x + v1.x) + (v2.x + v3.x)) + ((v4.x + v5.x) + (v6.x + v7.x));
                acc.y += ((v0.y + v1.y) + (v2.y + v3.y)) + ((v4.y + v5.y) + (v6.y + v7.y));
                acc.z += ((v0.z + v1.z) + (v2.z + v3.z)) + ((v4.z + v5.z) + (v6.z + v7.z));
                acc.w += ((v0.w + v1.w) + (v2.w + v3.w)) + ((v4.w + v5.w) + (v6.w + v7.w));
            }
            for (; e < end; e++) {
                float4 v = xw4[g_csrc[e] + lane];
                acc.x += v.x; acc.y += v.y; acc.z += v.z; acc.w += v.w;
            }
        } else {
            for (; e + 4 <= end; e += 4) {
                int s0 = g_csrc[e],     s1 = g_csrc[e + 1];
                int s2 = g_csrc[e + 2], s3 = g_csrc[e + 3];
                float n0 = g_deg[s0 >> 5], n1 = g_deg[s1 >> 5];
                float n2 = g_deg[s2 >> 5], n3 = g_deg[s3 >> 5];
                float4 v0 = xw4[s0 + lane];
                float4 v1 = xw4[s1 + lane];
                float4 v2 = xw4[s2 + lane];
                float4 v3 = xw4[s3 + lane];
                acc.x += (v0.x*n0 + v1.x*n1) + (v2.x*n2 + v3.x*n3);
                acc.y += (v0.y*n0 + v1.y*n1) + (v2.y*n2 + v3.y*n3);
                acc.z += (v0.z*n0 + v1.z*n1) + (v2.z*n2 + v3.z*n3);
                acc.w += (v0.w*n0 + v1.w*n1) + (v2.w*n2 + v3.w*n3);
            }
            for (; e < end; e++) {
                int s0 = g_csrc[e];
                float n0 = g_deg[s0 >> 5];
                float4 v = xw4[s0 + lane];
                acc.x += v.x*n0; acc.y += v.y*n0; acc.z += v.z*n0; acc.w += v.w*n0;
            }
        }

        float4 bb = ((const float4*)bias)[lane];
        float4 m = make_float4(acc.x * nd + bb.x, acc.y * nd + bb.y,
                               acc.z * nd + bb.z, acc.w * nd + bb.w);

        size_t off = (size_t)gw * D;
        const float* xprev = stage ? g_f1 : g_xT;
        float4 xv = ((const float4*)(xprev + off))[lane];

        float ms = m.x*m.x + m.y*m.y + m.z*m.z + m.w*m.w;
        float xs = xv.x*xv.x + xv.y*xv.y + xv.z*xv.z + xv.w*xv.w;
#pragma unroll
        for (int o = 16; o; o >>= 1) {
            ms += __shfl_xor_sync(0xFFFFFFFFu, ms, o);
            xs += __shfl_xor_sync(0xFFFFFFFFu, xs, o);
        }
        float coef = scale[0] * sqrtf(xs) / fmaxf(sqrtf(ms), 1e-12f);

        r.x = gelu_exact(xv.x + coef * m.x);
        r.y = gelu_exact(xv.y + coef * m.y);
        r.z = gelu_exact(xv.z + coef * m.z);
        r.w = gelu_exact(xv.w + coef * m.w);

        if (stage) {
            float4 rv = ((const float4*)(g_xT + off))[lane];
            r.x += rv.x; r.y += rv.y; r.z += rv.z; r.w += rv.w;
        }
        float* out = stage ? g_y : g_f1;
        ((float4*)(out + off))[lane] = r;
    }

    if (stage) {
        if (active) {
            int c0 = lane * 4;
            atomicAdd(&s_cs [c0    ], r.x); atomicAdd(&s_cs2[c0    ], r.x * r.x);
            atomicAdd(&s_cs [c0 + 1], r.y); atomicAdd(&s_cs2[c0 + 1], r.y * r.y);
            atomicAdd(&s_cs [c0 + 2], r.z); atomicAdd(&s_cs2[c0 + 2], r.z * r.z);
            atomicAdd(&s_cs [c0 + 3], r.w); atomicAdd(&s_cs2[c0 + 3], r.w * r.w);
        }
        __syncthreads();
        if (threadIdx.x < D) {
            atomicAdd(&g_cs [threadIdx.x], s_cs [threadIdx.x]);
            atomicAdd(&g_cs2[threadIdx.x], s_cs2[threadIdx.x]);
        }
    }
}

// ---------------- finalize: GraphNorm + GELU (+ restore g_hist = 0) --------
__global__ void k_final(const float* __restrict__ gnw,
                        const float* __restrict__ gnb,
                        const float* __restrict__ gnm,
                        float* __restrict__ out) {
    const float invN = 1.0f / (float)N_NODES;
    for (int idx = blockIdx.x * blockDim.x + threadIdx.x;
         idx < N_NODES * D; idx += gridDim.x * blockDim.x) {
        if (idx < N_NODES) g_hist[idx] = 0;     // self-restore for next replay
        int c = idx & (D - 1);
        float mean = g_cs[c]  * invN;
        float ey2  = g_cs2[c] * invN;
        float msc  = gnm[c];
        float sub  = g_y[idx] - mean * msc;
        float var  = ey2 - 2.0f * msc * mean * mean + msc * msc * mean * mean;
        float o = gnw[c] * sub * rsqrtf(var + 1e-5f) + gnb[c];
        out[idx] = gelu_exact(o);
    }
}

// ---------------- launch ----------------------------------------------------
extern "C" void kernel_launch(void* const* d_in, const int* in_sizes, int n_in,
                              void* d_out, int out_size) {
    const float* X   = (const float*)d_in[0];
    const int*   ei  = (const int*)  d_in[1];     // int32 (JAX x64 disabled)
    const float* W1  = (const float*)d_in[2];
    const float* b1  = (const float*)d_in[3];
    const float* s1  = (const float*)d_in[4];
    const float* W2  = (const float*)d_in[5];
    const float* b2  = (const float*)d_in[6];
    const float* s2  = (const float*)d_in[7];
    const float* gnw = (const float*)d_in[8];
    const float* gnb = (const float*)d_in[9];
    const float* gnm = (const float*)d_in[10];
    float* out = (float*)d_out;

    const int TB = 256;
    int gemm_blocks = (N_NODES + 127) / 128;
    int agg_blocks  = (N_NODES * 32 + 511) / 512;
    dim3 tg((N_NODES + 31) / 32, D / 32);

    cudaStream_t se;                       // edge-pipeline branch
    cudaStreamCreateWithFlags(&se, cudaStreamNonBlocking);
    cudaEvent_t evFork, evJoin;
    cudaEventCreateWithFlags(&evFork, cudaEventDisableTiming);
    cudaEventCreateWithFlags(&evJoin, cudaEventDisableTiming);

    // fork: edge pipeline on se, dense pipeline on default stream
    cudaEventRecord(evFork, 0);
    cudaStreamWaitEvent(se, evFork, 0);

    // branch A (se): CSR build + dinv (3 kernels now)
    k_deg   <<<(N_EDGES + TB - 1) / TB, TB, 0, se>>>(ei);
    k_scan1 <<<N_SBLK, SCAN_B, 0, se>>>();
    k_fill  <<<(N_EDGES + TB - 1) / TB, TB, 0, se>>>(ei);
    cudaEventRecord(evJoin, se);

    // branch B (default): transpose + raw GEMM layer 1
    k_transpose<<<tg, dim3(32, 8)>>>(X);
    k_gemm <<<gemm_blocks, TB>>>(0, W1);

    // join
    cudaStreamWaitEvent(0, evJoin, 0);

    // ---- layer 1 aggregation (applies dinv per edge) ----
    k_agg  <<<agg_blocks, 512>>>(0, b1, s1);

    // ---- layer 2 (pre-scaled path) ----
    k_gemm <<<gemm_blocks, TB>>>(1, W2);
    k_agg  <<<agg_blocks, 512>>>(1, b2, s2);

    // ---- GraphNorm + GELU ----
    k_final<<<4096, TB>>>(gnw, gnb, gnm, out);

    cudaEventDestroy(evFork);
    cudaEventDestroy(evJoin);
    cudaStreamDestroy(se);
}

// round 14
// speedup vs baseline: 1.1154x; 1.0504x over previous
#include <cuda_runtime.h>
#include <math.h>

#define N_NODES 50000
#define N_EDGES 800000
#define D 128
#define SCAN_B 1024
#define N_SBLK ((N_NODES + SCAN_B - 1) / SCAN_B)   // 49

// ---------------- scratch (device globals; self-restoring across replays) --
__device__ float g_xT [(size_t)N_NODES * D];   // X transposed: [N,128]
__device__ float g_xw [(size_t)N_NODES * D];   // GEMM out (L1 raw, L2 pre-scaled)
__device__ float g_f1 [(size_t)N_NODES * D];   // layer-1 output
__device__ float g_y  [(size_t)N_NODES * D];   // layer-2 output (+residual)
__device__ float g_deg[N_NODES];               // dinv = rsqrt(1 + in_deg)
__device__ int   g_hist[N_NODES];              // in-degree (zeroed by k_final)
__device__ int   g_rowstart[N_NODES];          // CSR row starts (by dst)
__device__ int   g_cursor[N_NODES];            // fill cursors
__device__ int   g_csrc[N_EDGES];              // CSR src indices
__device__ int   g_bsum[64];                   // scan block sums
__device__ float g_cs [D];                     // col sum of y  (zeroed by gemm L1)
__device__ float g_cs2[D];                     // col sum of y^2

// GELU exact via erff (short polynomial; ~1e-7 abs diff vs normcdff)
__device__ __forceinline__ float gelu_exact(float v) {
    return 0.5f * v * (1.0f + erff(v * 0.70710678118654752f));
}

__device__ __forceinline__ void fma2(unsigned long long& acc,
                                     unsigned long long a,
                                     unsigned long long b) {
    asm("fma.rn.f32x2 %0, %1, %2, %0;" : "+l"(acc) : "l"(a), "l"(b));
}

// ---------------- in-degree histogram (edge_index is INT32) ----------------
__global__ void k_deg(const int* __restrict__ ei) {
    int e = blockIdx.x * blockDim.x + threadIdx.x;
    if (e < N_EDGES) atomicAdd(&g_hist[ei[N_EDGES + e]], 1);
}

// ---------------- scan pass 1 (+ fused dinv = rsqrt(deg+1)) ----------------
__global__ void k_scan1() {
    __shared__ int sh[SCAN_B];
    int t = threadIdx.x;
    int i = blockIdx.x * SCAN_B + t;
    int v = (i < N_NODES) ? g_hist[i] : 0;
    if (i < N_NODES) g_deg[i] = rsqrtf((float)v + 1.0f);
    sh[t] = v;
    __syncthreads();
    for (int off = 1; off < SCAN_B; off <<= 1) {
        int x = (t >= off) ? sh[t - off] : 0;
        __syncthreads();
        sh[t] += x;
        __syncthreads();
    }
    if (i < N_NODES) g_rowstart[i] = sh[t] - v;
    if (t == SCAN_B - 1) g_bsum[blockIdx.x] = sh[t];
}

// ---------------- scan pass 2+3 fused: block offsets + apply ----------------
__global__ void k_scan3() {
    __shared__ int sb[64];
    int t = threadIdx.x;
    if (t < 64) sb[t] = (t < N_SBLK) ? g_bsum[t] : 0;
    __syncthreads();
#pragma unroll
    for (int off = 1; off < 64; off <<= 1) {
        int x = (t < 64 && t >= off) ? sb[t - off] : 0;
        __syncthreads();
        if (t < 64) sb[t] += x;
        __syncthreads();
    }
    int i = blockIdx.x * blockDim.x + t;
    if (i < N_NODES) {
        int blk = i / SCAN_B;
        int add = blk ? sb[blk - 1] : 0;
        int rs = g_rowstart[i] + add;
        g_rowstart[i] = rs;
        g_cursor[i]   = rs;
    }
}

// ---------------- CSR fill ---------------------------------------------------
__global__ void k_fill(const int* __restrict__ ei) {
    int e = blockIdx.x * blockDim.x + threadIdx.x;
    if (e < N_EDGES) {
        int s = ei[e];
        int d = ei[N_EDGES + e];
        int pos = atomicAdd(&g_cursor[d], 1);
        g_csrc[pos] = s;
    }
}

// ---------------- transpose X [128,N] -> xT [N,128] ------------------------
__global__ void k_transpose(const float* __restrict__ X) {
    __shared__ float s[32][33];
    int n0 = blockIdx.x * 32;
    int f0 = blockIdx.y * 32;
    int tx = threadIdx.x, ty = threadIdx.y;          // (32, 8)
    int n = n0 + tx;
#pragma unroll
    for (int i = 0; i < 4; i++) {
        int f = f0 + ty + i * 8;
        if (n < N_NODES) s[ty + i * 8][tx] = X[(size_t)f * N_NODES + n];
    }
    __syncthreads();
#pragma unroll
    for (int i = 0; i < 4; i++) {
        int n2 = n0 + ty + i * 8;
        int f2 = f0 + tx;
        if (n2 < N_NODES) g_xT[(size_t)n2 * D + f2] = s[tx][ty + i * 8];
    }
}

// ---------------- GEMM (f32x2) ----------------------------------------------
// Layer 1 (src_sel=0): g_xw = A @ W          (raw; dinv applied in agg stage 0)
// Layer 2 (src_sel=1): g_xw = (A @ W)*dinv   (pre-scaled fast path)
__global__ void __launch_bounds__(256) k_gemm(int src_sel,
                                              const float* __restrict__ W) {
    const float* __restrict__ A = src_sel ? g_f1 : g_xT;
    if (src_sel == 0 && blockIdx.x == 0 && threadIdx.x < D) {
        g_cs[threadIdx.x] = 0.0f;
        g_cs2[threadIdx.x] = 0.0f;
    }
    __shared__ float2 As2[128][16];    // 16 KB: (a,a) pairs, 16-col k-chunk
    __shared__ float  Ws[16][132];     // 8.25 KB padded
    int t  = threadIdx.x;
    int tx = t & 15;                   // column group (8 cols)
    int ty = t >> 4;                   // node group (8 nodes)
    int nbase = blockIdx.x * 128;

    unsigned long long acc[8][4];
#pragma unroll
    for (int i = 0; i < 8; i++)
#pragma unroll
        for (int p = 0; p < 4; p++) acc[i][p] = 0ull;

    for (int fc = 0; fc < D; fc += 16) {
#pragma unroll
        for (int k = 0; k < 8; k++) {           // 128x16 A chunk (dup pairs)
            int idx = t + k * 256;
            int r = idx >> 4, c = idx & 15;
            int n = nbase + r;
            float v = (n < N_NODES) ? A[(size_t)n * D + fc + c] : 0.0f;
            As2[r][c] = make_float2(v, v);
        }
#pragma unroll
        for (int k = 0; k < 8; k++) {           // 16x128 W chunk
            int idx = t + k * 256;
            int r = idx >> 7, c = idx & 127;
            Ws[r][c] = W[(fc + r) * D + c];
        }
        __syncthreads();
#pragma unroll
        for (int ff = 0; ff < 16; ff++) {
            const unsigned long long* wrow =
                (const unsigned long long*)&Ws[ff][tx * 8];
            unsigned long long w0 = wrow[0];
            unsigned long long w1 = wrow[1];
            unsigned long long w2 = wrow[2];
            unsigned long long w3 = wrow[3];
#pragma unroll
            for (int i = 0; i < 8; i++) {
                unsigned long long a2 =
                    *(const unsigned long long*)&As2[ty * 8 + i][ff];
                fma2(acc[i][0], a2, w0);
                fma2(acc[i][1], a2, w1);
                fma2(acc[i][2], a2, w2);
                fma2(acc[i][3], a2, w3);
            }
        }
        __syncthreads();
    }

#pragma unroll
    for (int i = 0; i < 8; i++) {
        int node = nbase + ty * 8 + i;
        if (node >= N_NODES) continue;
        float di = src_sel ? g_deg[node] : 1.0f;
        size_t off = (size_t)node * D + tx * 8;
        float2 p0 = *(float2*)&acc[i][0];
        float2 p1 = *(float2*)&acc[i][1];
        float2 p2 = *(float2*)&acc[i][2];
        float2 p3 = *(float2*)&acc[i][3];
        ((float4*)(g_xw + off))[0] =
            make_float4(p0.x * di, p0.y * di, p1.x * di, p1.y * di);
        ((float4*)(g_xw + off))[1] =
            make_float4(p2.x * di, p2.y * di, p3.x * di, p3.y * di);
    }
}

// ---------------- fused CSR gather + MessageNorm + GELU (+stats) -----------
// stage 0: xw raw   -> msg = dinv[d]*(dinv[d]*xw[d] + sum dinv[s]*xw[s]) + b
// stage 1: xw scaled-> msg = dinv[d]*(xw[d] + sum xw[s]) + b   (+res, +stats)
// CSR index loads vectorized (int4 after 4-alignment head loop).
__global__ void __launch_bounds__(512) k_agg(int stage,
                                             const float* __restrict__ bias,
                                             const float* __restrict__ scale) {
    __shared__ float s_cs[D], s_cs2[D];
    if (stage) {
        if (threadIdx.x < D) { s_cs[threadIdx.x] = 0.0f; s_cs2[threadIdx.x] = 0.0f; }
        __syncthreads();
    }

    int gw = (blockIdx.x * blockDim.x + threadIdx.x) >> 5;
    int lane = threadIdx.x & 31;
    bool active = gw < N_NODES;
    float4 r = make_float4(0.f, 0.f, 0.f, 0.f);

    if (active) {
        const float4* xw4 = (const float4*)g_xw;
        float nd = g_deg[gw];
        float4 acc = xw4[(size_t)gw * 32 + lane];       // self-loop term
        if (!stage) { acc.x *= nd; acc.y *= nd; acc.z *= nd; acc.w *= nd; }
        int rs  = g_rowstart[gw];
        int end = rs + g_hist[gw];
        int e = rs;
        if (stage) {
            // head: align e to 4 for int4 index loads
            for (; e < end && (e & 3); e++) {
                float4 v = xw4[(size_t)g_csrc[e] * 32 + lane];
                acc.x += v.x; acc.y += v.y; acc.z += v.z; acc.w += v.w;
            }
            for (; e + 8 <= end; e += 8) {
                int4 ia = *(const int4*)&g_csrc[e];
                int4 ib = *(const int4*)&g_csrc[e + 4];
                float4 v0 = xw4[(size_t)ia.x * 32 + lane];
                float4 v1 = xw4[(size_t)ia.y * 32 + lane];
                float4 v2 = xw4[(size_t)ia.z * 32 + lane];
                float4 v3 = xw4[(size_t)ia.w * 32 + lane];
                float4 v4 = xw4[(size_t)ib.x * 32 + lane];
                float4 v5 = xw4[(size_t)ib.y * 32 + lane];
                float4 v6 = xw4[(size_t)ib.z * 32 + lane];
                float4 v7 = xw4[(size_t)ib.w * 32 + lane];
                acc.x += ((v0.x + v1.x) + (v2.x + v3.x)) + ((v4.x + v5.x) + (v6.x + v7.x));
                acc.y += ((v0.y + v1.y) + (v2.y + v3.y)) + ((v4.y + v5.y) + (v6.y + v7.y));
                acc.z += ((v0.z + v1.z) + (v2.z + v3.z)) + ((v4.z + v5.z) + (v6.z + v7.z));
                acc.w += ((v0.w + v1.w) + (v2.w + v3.w)) + ((v4.w + v5.w) + (v6.w + v7.w));
            }
            for (; e < end; e++) {
                float4 v = xw4[(size_t)g_csrc[e] * 32 + lane];
                acc.x += v.x; acc.y += v.y; acc.z += v.z; acc.w += v.w;
            }
        } else {
            for (; e < end && (e & 3); e++) {
                int s0 = g_csrc[e];
                float n0 = g_deg[s0];
                float4 v = xw4[(size_t)s0 * 32 + lane];
                acc.x += v.x*n0; acc.y += v.y*n0; acc.z += v.z*n0; acc.w += v.w*n0;
            }
            for (; e + 4 <= end; e += 4) {
                int4 ia = *(const int4*)&g_csrc[e];
                float n0 = g_deg[ia.x], n1 = g_deg[ia.y];
                float n2 = g_deg[ia.z], n3 = g_deg[ia.w];
                float4 v0 = xw4[(size_t)ia.x * 32 + lane];
                float4 v1 = xw4[(size_t)ia.y * 32 + lane];
                float4 v2 = xw4[(size_t)ia.z * 32 + lane];
                float4 v3 = xw4[(size_t)ia.w * 32 + lane];
                acc.x += (v0.x*n0 + v1.x*n1) + (v2.x*n2 + v3.x*n3);
                acc.y += (v0.y*n0 + v1.y*n1) + (v2.y*n2 + v3.y*n3);
                acc.z += (v0.z*n0 + v1.z*n1) + (v2.z*n2 + v3.z*n3);
                acc.w += (v0.w*n0 + v1.w*n1) + (v2.w*n2 + v3.w*n3);
            }
            for (; e < end; e++) {
                int s0 = g_csrc[e];
                float n0 = g_deg[s0];
                float4 v = xw4[(size_t)s0 * 32 + lane];
                acc.x += v.x*n0; acc.y += v.y*n0; acc.z += v.z*n0; acc.w += v.w*n0;
            }
        }

        float4 bb = ((const float4*)bias)[lane];
        float4 m = make_float4(acc.x * nd + bb.x, acc.y * nd + bb.y,
                               acc.z * nd + bb.z, acc.w * nd + bb.w);

        size_t off = (size_t)gw * D;
        const float* xprev = stage ? g_f1 : g_xT;
        float4 xv = ((const float4*)(xprev + off))[lane];

        float ms = m.x*m.x + m.y*m.y + m.z*m.z + m.w*m.w;
        float xs = xv.x*xv.x + xv.y*xv.y + xv.z*xv.z + xv.w*xv.w;
#pragma unroll
        for (int o = 16; o; o >>= 1) {
            ms += __shfl_xor_sync(0xFFFFFFFFu, ms, o);
            xs += __shfl_xor_sync(0xFFFFFFFFu, xs, o);
        }
        float coef = scale[0] * sqrtf(xs) / fmaxf(sqrtf(ms), 1e-12f);

        r.x = gelu_exact(xv.x + coef * m.x);
        r.y = gelu_exact(xv.y + coef * m.y);
        r.z = gelu_exact(xv.z + coef * m.z);
        r.w = gelu_exact(xv.w + coef * m.w);

        if (stage) {
            float4 rv = ((const float4*)(g_xT + off))[lane];
            r.x += rv.x; r.y += rv.y; r.z += rv.z; r.w += rv.w;
        }
        float* out = stage ? g_y : g_f1;
        ((float4*)(out + off))[lane] = r;
    }

    if (stage) {
        if (active) {
            int c0 = lane * 4;
            atomicAdd(&s_cs [c0    ], r.x); atomicAdd(&s_cs2[c0    ], r.x * r.x);
            atomicAdd(&s_cs [c0 + 1], r.y); atomicAdd(&s_cs2[c0 + 1], r.y * r.y);
            atomicAdd(&s_cs [c0 + 2], r.z); atomicAdd(&s_cs2[c0 + 2], r.z * r.z);
            atomicAdd(&s_cs [c0 + 3], r.w); atomicAdd(&s_cs2[c0 + 3], r.w * r.w);
        }
        __syncthreads();
        if (threadIdx.x < D) {
            atomicAdd(&g_cs [threadIdx.x], s_cs [threadIdx.x]);
            atomicAdd(&g_cs2[threadIdx.x], s_cs2[threadIdx.x]);
        }
    }
}

// ---------------- finalize: GraphNorm + GELU, float4 (+ g_hist restore) ----
__global__ void k_final(const float* __restrict__ gnw,
                        const float* __restrict__ gnb,
                        const float* __restrict__ gnm,
                        float* __restrict__ out) {
    const float invN = 1.0f / (float)N_NODES;
    int gtid = blockIdx.x * blockDim.x + threadIdx.x;
    int gstride = gridDim.x * blockDim.x;
    // restore g_hist for next replay
    for (int i = gtid; i < N_NODES; i += gstride) g_hist[i] = 0;
    // GraphNorm + GELU, 4 elems per thread
    const int total4 = N_NODES * D / 4;
    for (int q = gtid; q < total4; q += gstride) {
        int c0 = (q * 4) & (D - 1);
        float4 y  = ((const float4*)g_y)[q];
        float4 w4  = *(const float4*)&gnw[c0];
        float4 b4  = *(const float4*)&gnb[c0];
        float4 ms4 = *(const float4*)&gnm[c0];
        float4 cs  = *(const float4*)&g_cs[c0];
        float4 cs2 = *(const float4*)&g_cs2[c0];
        float4 o;
        {
            float mean = cs.x * invN, ey2 = cs2.x * invN, msc = ms4.x;
            float var = ey2 - 2.0f*msc*mean*mean + msc*msc*mean*mean;
            o.x = gelu_exact(w4.x * (y.x - mean*msc) * rsqrtf(var + 1e-5f) + b4.x);
        }
        {
            float mean = cs.y * invN, ey2 = cs2.y * invN, msc = ms4.y;
            float var = ey2 - 2.0f*msc*mean*mean + msc*msc*mean*mean;
            o.y = gelu_exact(w4.y * (y.y - mean*msc) * rsqrtf(var + 1e-5f) + b4.y);
        }
        {
            float mean = cs.z * invN, ey2 = cs2.z * invN, msc = ms4.z;
            float var = ey2 - 2.0f*msc*mean*mean + msc*msc*mean*mean;
            o.z = gelu_exact(w4.z * (y.z - mean*msc) * rsqrtf(var + 1e-5f) + b4.z);
        }
        {
            float mean = cs.w * invN, ey2 = cs2.w * invN, msc = ms4.w;
            float var = ey2 - 2.0f*msc*mean*mean + msc*msc*mean*mean;
            o.w = gelu_exact(w4.w * (y.w - mean*msc) * rsqrtf(var + 1e-5f) + b4.w);
        }
        ((float4*)out)[q] = o;
    }
}

// ---------------- launch ----------------------------------------------------
extern "C" void kernel_launch(void* const* d_in, const int* in_sizes, int n_in,
                              void* d_out, int out_size) {
    const float* X   = (const float*)d_in[0];
    const int*   ei  = (const int*)  d_in[1];     // int32 (JAX x64 disabled)
    const float* W1  = (const float*)d_in[2];
    const float* b1  = (const float*)d_in[3];
    const float* s1  = (const float*)d_in[4];
    const float* W2  = (const float*)d_in[5];
    const float* b2  = (const float*)d_in[6];
    const float* s2  = (const float*)d_in[7];
    const float* gnw = (const float*)d_in[8];
    const float* gnb = (const float*)d_in[9];
    const float* gnm = (const float*)d_in[10];
    float* out = (float*)d_out;

    const int TB = 256;
    int gemm_blocks = (N_NODES + 127) / 128;
    int agg_blocks  = (N_NODES * 32 + 511) / 512;
    dim3 tg((N_NODES + 31) / 32, D / 32);

    cudaStream_t se;                       // edge-pipeline branch
    cudaStreamCreateWithFlags(&se, cudaStreamNonBlocking);
    cudaEvent_t evFork, evJoin;
    cudaEventCreateWithFlags(&evFork, cudaEventDisableTiming);
    cudaEventCreateWithFlags(&evJoin, cudaEventDisableTiming);

    // fork: edge pipeline on se, dense pipeline on default stream
    cudaEventRecord(evFork, 0);
    cudaStreamWaitEvent(se, evFork, 0);

    // branch A (se): CSR build + dinv
    k_deg   <<<(N_EDGES + TB - 1) / TB, TB, 0, se>>>(ei);
    k_scan1 <<<N_SBLK, SCAN_B, 0, se>>>();
    k_scan3 <<<(N_NODES + TB - 1) / TB, TB, 0, se>>>();
    k_fill  <<<(N_EDGES + TB - 1) / TB, TB, 0, se>>>(ei);
    cudaEventRecord(evJoin, se);

    // branch B (default): transpose + raw GEMM layer 1
    k_transpose<<<tg, dim3(32, 8)>>>(X);
    k_gemm <<<gemm_blocks, TB>>>(0, W1);

    // join
    cudaStreamWaitEvent(0, evJoin, 0);

    // ---- layer 1 aggregation (applies dinv per edge) ----
    k_agg  <<<agg_blocks, 512>>>(0, b1, s1);

    // ---- layer 2 (pre-scaled path) ----
    k_gemm <<<gemm_blocks, TB>>>(1, W2);
    k_agg  <<<agg_blocks, 512>>>(1, b2, s2);

    // ---- GraphNorm + GELU ----
    k_final<<<2048, TB>>>(gnw, gnb, gnm, out);

    cudaEventDestroy(evFork);
    cudaEventDestroy(evJoin);
    cudaStreamDestroy(se);
}